// round 5
// baseline (speedup 1.0000x reference)
#include <cuda_runtime.h>
#include <cuda_bf16.h>

// =====================================================================
// ATQCNN factorization:
//   U = fixed 128x128 orthogonal circuit matrix (wires 0..6; 7,8 inert)
//   Y[b] = U x[b];  q[b,k] = sum_{m&3==k} Y[b,m]^2;  out = softmax(q/sum q)
// Kernel 1: warp-per-basis register simulation (shfl, no barriers).
// Kernel 2: 4096x128x128 fp32 GEMM w/ squared-sum + softmax epilogue.
//           512 blocks x 128 thr, warp = 2 batches, A+X register prefetch.
// =====================================================================

__device__ float g_AT[128 * 128];   // g_AT[i*128 + m] = <m| U |i>

// --------------------- gate primitives (register sim) -----------------
// Amp index m (7 bits): bits[6:2] = lane, bits[1:0] = register r.
// Bit position of wire w is P = 6 - w.

template<int P>
__device__ __forceinline__ void ry_p(float a[4], float c, float s, int lane) {
    if constexpr (P == 0) {                 // wire 6: pairs (a0,a1),(a2,a3)
        float n0 = c * a[0] - s * a[1];
        float n1 = fmaf(s, a[0], c * a[1]);
        float n2 = c * a[2] - s * a[3];
        float n3 = fmaf(s, a[2], c * a[3]);
        a[0] = n0; a[1] = n1; a[2] = n2; a[3] = n3;
    } else if constexpr (P == 1) {          // wire 5: pairs (a0,a2),(a1,a3)
        float n0 = c * a[0] - s * a[2];
        float n2 = fmaf(s, a[0], c * a[2]);
        float n1 = c * a[1] - s * a[3];
        float n3 = fmaf(s, a[1], c * a[3]);
        a[0] = n0; a[1] = n1; a[2] = n2; a[3] = n3;
    } else {                                // cross-lane wire
        constexpr int M = 1 << (P - 2);
        const float sgn = (lane & M) ? s : -s;
        #pragma unroll
        for (int r = 0; r < 4; ++r) {
            float pr = __shfl_xor_sync(0xffffffffu, a[r], M);
            a[r] = fmaf(sgn, pr, c * a[r]);
        }
    }
}

template<int W>
__device__ __forceinline__ void ry_w(float a[4], float2 cs, int lane) {
    ry_p<6 - W>(a, cs.x, cs.y, lane);
}

template<int PC, int PT>
__device__ __forceinline__ void cnot_p(float a[4], int lane) {
    if constexpr (PT >= 2) {                // target is a lane bit
        constexpr int MT = 1 << (PT - 2);
        if constexpr (PC >= 2) {            // control is a lane bit
            constexpr int MC = 1 << (PC - 2);
            const bool ctl = (lane & MC) != 0;
            #pragma unroll
            for (int r = 0; r < 4; ++r) {
                float pr = __shfl_xor_sync(0xffffffffu, a[r], MT);
                a[r] = ctl ? pr : a[r];
            }
        } else {                            // control in-register bit PC
            #pragma unroll
            for (int r = 0; r < 4; ++r) {
                if ((r >> PC) & 1) {        // compile-time constant after unroll
                    a[r] = __shfl_xor_sync(0xffffffffu, a[r], MT);
                }
            }
        }
    } else {                                // target in-register
        if constexpr (PC >= 2) {            // control is a lane bit
            constexpr int MC = 1 << (PC - 2);
            const bool ctl = (lane & MC) != 0;
            if constexpr (PT == 0) {        // swap (a0,a1) and (a2,a3)
                float t0 = a[0], t2 = a[2];
                a[0] = ctl ? a[1] : a[0];  a[1] = ctl ? t0 : a[1];
                a[2] = ctl ? a[3] : a[2];  a[3] = ctl ? t2 : a[3];
            } else {                        // PT == 1: swap (a0,a2),(a1,a3)
                float t0 = a[0], t1 = a[1];
                a[0] = ctl ? a[2] : a[0];  a[2] = ctl ? t0 : a[2];
                a[1] = ctl ? a[3] : a[1];  a[3] = ctl ? t1 : a[3];
            }
        } else {                            // both in-register
            if constexpr (PC == 1 && PT == 0) { float t = a[2]; a[2] = a[3]; a[3] = t; }
            else                              { float t = a[1]; a[1] = a[3]; a[3] = t; }
        }
    }
}

template<int C, int T>
__device__ __forceinline__ void cnot_w(float a[4], int lane) {
    cnot_p<6 - C, 6 - T>(a, lane);
}

template<int WA, int WB>
__device__ __forceinline__ void conv6(float a[4], int lane,
                                      const float2* __restrict__ cs, int base) {
    #pragma unroll
    for (int q = 0; q < 6; ++q) {
        ry_w<WA>(a, cs[base + 2 * q], lane);
        ry_w<WB>(a, cs[base + 2 * q + 1], lane);
        cnot_w<WA, WB>(a, lane);
    }
}

// ----------------------------- Kernel 1 ------------------------------
// 16 blocks x 256 threads; one warp per basis state, no per-gate barriers.
__global__ __launch_bounds__(256) void build_A_kernel(
        const float* __restrict__ QC1, const float* __restrict__ QC2,
        const float* __restrict__ QC3, const float* __restrict__ QP1,
        const float* __restrict__ QP2, const float* __restrict__ QP3,
        const float* __restrict__ QF) {
    __shared__ float2 cs[46];
    const int tid  = threadIdx.x;
    const int lane = tid & 31;
    const int basis = blockIdx.x * 8 + (tid >> 5);

    if (tid < 46) {
        float ang;
        if      (tid < 12) ang = QC1[tid];
        else if (tid < 24) ang = QC2[tid - 12];
        else if (tid < 36) ang = QC3[tid - 24];
        else if (tid == 36) ang =  QP1[0];
        else if (tid == 37) ang =  QP1[1];
        else if (tid == 38) ang = -QP1[1];
        else if (tid == 39) ang =  QP2[0];
        else if (tid == 40) ang =  QP2[1];
        else if (tid == 41) ang = -QP2[1];
        else if (tid == 42) ang =  QP3[0];
        else if (tid == 43) ang =  QP3[1];
        else if (tid == 44) ang = -QP3[1];
        else               ang = QF[0] + QF[1] + QF[2] + QF[3];  // RY angles add
        float sn, c;
        sincosf(0.5f * ang, &sn, &c);
        cs[tid] = make_float2(c, sn);
    }
    __syncthreads();   // the only barrier

    float a[4];
    #pragma unroll
    for (int r = 0; r < 4; ++r) a[r] = (lane * 4 + r == basis) ? 1.0f : 0.0f;

    // conv block 1: pairs (i, (i+1)%7)
    conv6<0,1>(a, lane, cs, 0);  conv6<1,2>(a, lane, cs, 0);
    conv6<2,3>(a, lane, cs, 0);  conv6<3,4>(a, lane, cs, 0);
    conv6<4,5>(a, lane, cs, 0);  conv6<5,6>(a, lane, cs, 0);
    conv6<6,0>(a, lane, cs, 0);
    // pool 1
    ry_w<0>(a, cs[36], lane); ry_w<3>(a, cs[37], lane);
    cnot_w<0,3>(a, lane);     ry_w<3>(a, cs[38], lane);
    ry_w<1>(a, cs[36], lane); ry_w<4>(a, cs[37], lane);
    cnot_w<1,4>(a, lane);     ry_w<4>(a, cs[38], lane);
    ry_w<2>(a, cs[36], lane); ry_w<5>(a, cs[37], lane);
    cnot_w<2,5>(a, lane);     ry_w<5>(a, cs[38], lane);
    // conv block 2
    conv6<3,4>(a, lane, cs, 12);
    conv6<4,5>(a, lane, cs, 12);
    conv6<5,6>(a, lane, cs, 12);
    #pragma unroll
    for (int q = 0; q < 6; ++q) {           // i == 6 special case
        ry_w<6>(a, cs[12 + 2 * q], lane);
        ry_w<3>(a, cs[13 + 2 * q], lane);
        cnot_w<6,0>(a, lane);
    }
    // pool 2
    ry_w<3>(a, cs[39], lane); ry_w<5>(a, cs[40], lane);
    cnot_w<3,5>(a, lane);     ry_w<5>(a, cs[41], lane);
    ry_w<4>(a, cs[39], lane); ry_w<6>(a, cs[40], lane);
    cnot_w<4,6>(a, lane);     ry_w<6>(a, cs[41], lane);
    // conv block 3 (reference bug preserved: CNOT(4,5))
    #pragma unroll
    for (int q = 0; q < 6; ++q) {
        ry_w<5>(a, cs[24 + 2 * q], lane);
        ry_w<6>(a, cs[25 + 2 * q], lane);
        cnot_w<4,5>(a, lane);
    }
    // pool 3 (reference bug preserved: CNOT(4,6))
    ry_w<5>(a, cs[42], lane); ry_w<6>(a, cs[43], lane);
    cnot_w<4,6>(a, lane);     ry_w<6>(a, cs[44], lane);
    // final: 4x RY(5) fused; CNOT(7,5)/CNOT(8,6) identity (ctrl |0>)
    ry_w<5>(a, cs[45], lane);
    cnot_w<5,6>(a, lane);
    cnot_w<6,5>(a, lane);

    reinterpret_cast<float4*>(g_AT)[basis * 32 + lane] =
        make_float4(a[0], a[1], a[2], a[3]);
}

// ----------------------------- Kernel 2 ------------------------------
// 512 blocks x 128 threads. Block = 8 batches, warp = 2 batches.
// Lane owns output rows m = 4*lane..4*lane+3 (component c == group k).
// A and X are register double-buffered (prefetch one i-group ahead;
// the tail prefetch wraps with &31 so nothing is out of bounds).

#define APPLY_BATCH_PER_BLOCK 8
#define APPLY_THREADS 128
#define AS4_COUNT (32 * 128)                       // 64 KB
#define XS4_COUNT (APPLY_BATCH_PER_BLOCK * 32)     // 4 KB

__device__ __forceinline__ void fma4(float4& acc, float xs, const float4& a) {
    acc.x = fmaf(xs, a.x, acc.x);
    acc.y = fmaf(xs, a.y, acc.y);
    acc.z = fmaf(xs, a.z, acc.z);
    acc.w = fmaf(xs, a.w, acc.w);
}

__global__ __launch_bounds__(APPLY_THREADS) void qcnn_apply_kernel(
        const float* __restrict__ X, float* __restrict__ out) {
    extern __shared__ float sm[];
    float4* As4 = reinterpret_cast<float4*>(sm);
    float4* Xs4 = reinterpret_cast<float4*>(sm) + AS4_COUNT;

    const int tid  = threadIdx.x;
    const int warp = tid >> 5;
    const int lane = tid & 31;
    const int bbase = blockIdx.x * APPLY_BATCH_PER_BLOCK;

    // Stage A^T (64 KB) and the X tile (4 KB), coalesced float4.
    const float4* gA4 = reinterpret_cast<const float4*>(g_AT);
    #pragma unroll
    for (int k = 0; k < AS4_COUNT / APPLY_THREADS; ++k)
        As4[tid + k * APPLY_THREADS] = gA4[tid + k * APPLY_THREADS];
    const float4* gX4 = reinterpret_cast<const float4*>(X + (size_t)bbase * 128);
    #pragma unroll
    for (int k = 0; k < XS4_COUNT / APPLY_THREADS; ++k)
        Xs4[tid + k * APPLY_THREADS] = gX4[tid + k * APPLY_THREADS];
    __syncthreads();

    const float4* Xw   = Xs4 + warp * 2 * 32;   // 2 batches per warp
    const float4* Arow = As4 + lane;            // lane's 4 output columns

    float4 acc0 = {0,0,0,0}, acc1 = {0,0,0,0};

    // Prime the pipeline: i-group 0.
    float4 c0 = Arow[0], c1 = Arow[32], c2 = Arow[64], c3 = Arow[96];
    float4 x0 = Xw[0],  x1 = Xw[32];

    #pragma unroll 4
    for (int i4 = 0; i4 < 32; ++i4) {
        // Prefetch next i-group (wraps to 0 on the last iteration).
        const int nxt = (i4 + 1) & 31;
        const float4* An = Arow + nxt * 128;
        float4 n0 = An[0], n1 = An[32], n2 = An[64], n3 = An[96];
        float4 xn0 = Xw[nxt], xn1 = Xw[32 + nxt];

        fma4(acc0, x0.x, c0);  fma4(acc1, x1.x, c0);
        fma4(acc0, x0.y, c1);  fma4(acc1, x1.y, c1);
        fma4(acc0, x0.z, c2);  fma4(acc1, x1.z, c2);
        fma4(acc0, x0.w, c3);  fma4(acc1, x1.w, c3);

        c0 = n0; c1 = n1; c2 = n2; c3 = n3;
        x0 = xn0; x1 = xn1;
    }

    #pragma unroll
    for (int g = 0; g < 2; ++g) {
        const float4 acc = g ? acc1 : acc0;
        float q0 = acc.x * acc.x;
        float q1 = acc.y * acc.y;
        float q2 = acc.z * acc.z;
        float q3 = acc.w * acc.w;
        #pragma unroll
        for (int off = 16; off; off >>= 1) {
            q0 += __shfl_xor_sync(0xffffffffu, q0, off);
            q1 += __shfl_xor_sync(0xffffffffu, q1, off);
            q2 += __shfl_xor_sync(0xffffffffu, q2, off);
            q3 += __shfl_xor_sync(0xffffffffu, q3, off);
        }
        if (lane == 0) {
            const float S = q0 + q1 + q2 + q3;   // == ||x||^2 (U orthogonal)
            const float inv_s = 1.0f / S;
            const float p0 = q0 * inv_s, p1 = q1 * inv_s;
            const float p2 = q2 * inv_s, p3 = q3 * inv_s;
            const float mx = fmaxf(fmaxf(p0, p1), fmaxf(p2, p3));
            const float e0 = expf(p0 - mx), e1 = expf(p1 - mx);
            const float e2 = expf(p2 - mx), e3 = expf(p3 - mx);
            const float inv = 1.0f / (e0 + e1 + e2 + e3);
            reinterpret_cast<float4*>(out)[bbase + warp * 2 + g] =
                make_float4(e0 * inv, e1 * inv, e2 * inv, e3 * inv);
        }
    }
}

// ----------------------------- launch --------------------------------
extern "C" void kernel_launch(void* const* d_in, const int* in_sizes, int n_in,
                              void* d_out, int out_size) {
    const float* x   = (const float*)d_in[0];
    const float* QC1 = (const float*)d_in[1];
    const float* QC2 = (const float*)d_in[2];
    const float* QC3 = (const float*)d_in[3];
    const float* QP1 = (const float*)d_in[4];
    const float* QP2 = (const float*)d_in[5];
    const float* QP3 = (const float*)d_in[6];
    const float* QF  = (const float*)d_in[7];

    const int B = in_sizes[0] / 128;

    build_A_kernel<<<16, 256>>>(QC1, QC2, QC3, QP1, QP2, QP3, QF);

    const int smem_bytes = (AS4_COUNT + XS4_COUNT) * sizeof(float4);  // 68 KB
    cudaFuncSetAttribute(qcnn_apply_kernel,
                         cudaFuncAttributeMaxDynamicSharedMemorySize, smem_bytes);
    qcnn_apply_kernel<<<B / APPLY_BATCH_PER_BLOCK, APPLY_THREADS, smem_bytes>>>(
        x, (float*)d_out);
}

// round 6
// speedup vs baseline: 1.2558x; 1.2558x over previous
#include <cuda_runtime.h>
#include <cuda_bf16.h>

// =====================================================================
// ATQCNN factorization:
//   U = fixed 128x128 orthogonal circuit matrix (wires 0..6; 7,8 inert)
//   Y[b] = U x[b];  q[b,k] = sum_{m&3==k} Y[b,m]^2;  out = softmax(q/sum q)
// Kernel 1: warp-per-basis register simulation (shfl, no barriers).
// Kernel 2: 4096x128x128 fp32 GEMM w/ squared-sum + softmax epilogue.
//           256 blocks x 64 thr, warp = 8 batches (128 FFMA per 24 smem
//           wavefronts), A register double-buffered.
// =====================================================================

__device__ float g_AT[128 * 128];   // g_AT[i*128 + m] = <m| U |i>

// --------------------- gate primitives (register sim) -----------------
// Amp index m (7 bits): bits[6:2] = lane, bits[1:0] = register r.
// Bit position of wire w is P = 6 - w.

template<int P>
__device__ __forceinline__ void ry_p(float a[4], float c, float s, int lane) {
    if constexpr (P == 0) {                 // wire 6: pairs (a0,a1),(a2,a3)
        float n0 = c * a[0] - s * a[1];
        float n1 = fmaf(s, a[0], c * a[1]);
        float n2 = c * a[2] - s * a[3];
        float n3 = fmaf(s, a[2], c * a[3]);
        a[0] = n0; a[1] = n1; a[2] = n2; a[3] = n3;
    } else if constexpr (P == 1) {          // wire 5: pairs (a0,a2),(a1,a3)
        float n0 = c * a[0] - s * a[2];
        float n2 = fmaf(s, a[0], c * a[2]);
        float n1 = c * a[1] - s * a[3];
        float n3 = fmaf(s, a[1], c * a[3]);
        a[0] = n0; a[1] = n1; a[2] = n2; a[3] = n3;
    } else {                                // cross-lane wire
        constexpr int M = 1 << (P - 2);
        const float sgn = (lane & M) ? s : -s;
        #pragma unroll
        for (int r = 0; r < 4; ++r) {
            float pr = __shfl_xor_sync(0xffffffffu, a[r], M);
            a[r] = fmaf(sgn, pr, c * a[r]);
        }
    }
}

template<int W>
__device__ __forceinline__ void ry_w(float a[4], float2 cs, int lane) {
    ry_p<6 - W>(a, cs.x, cs.y, lane);
}

template<int PC, int PT>
__device__ __forceinline__ void cnot_p(float a[4], int lane) {
    if constexpr (PT >= 2) {                // target is a lane bit
        constexpr int MT = 1 << (PT - 2);
        if constexpr (PC >= 2) {            // control is a lane bit
            constexpr int MC = 1 << (PC - 2);
            const bool ctl = (lane & MC) != 0;
            #pragma unroll
            for (int r = 0; r < 4; ++r) {
                float pr = __shfl_xor_sync(0xffffffffu, a[r], MT);
                a[r] = ctl ? pr : a[r];
            }
        } else {                            // control in-register bit PC
            #pragma unroll
            for (int r = 0; r < 4; ++r) {
                if ((r >> PC) & 1) {        // compile-time constant after unroll
                    a[r] = __shfl_xor_sync(0xffffffffu, a[r], MT);
                }
            }
        }
    } else {                                // target in-register
        if constexpr (PC >= 2) {            // control is a lane bit
            constexpr int MC = 1 << (PC - 2);
            const bool ctl = (lane & MC) != 0;
            if constexpr (PT == 0) {        // swap (a0,a1) and (a2,a3)
                float t0 = a[0], t2 = a[2];
                a[0] = ctl ? a[1] : a[0];  a[1] = ctl ? t0 : a[1];
                a[2] = ctl ? a[3] : a[2];  a[3] = ctl ? t2 : a[3];
            } else {                        // PT == 1: swap (a0,a2),(a1,a3)
                float t0 = a[0], t1 = a[1];
                a[0] = ctl ? a[2] : a[0];  a[2] = ctl ? t0 : a[2];
                a[1] = ctl ? a[3] : a[1];  a[3] = ctl ? t1 : a[3];
            }
        } else {                            // both in-register
            if constexpr (PC == 1 && PT == 0) { float t = a[2]; a[2] = a[3]; a[3] = t; }
            else                              { float t = a[1]; a[1] = a[3]; a[3] = t; }
        }
    }
}

template<int C, int T>
__device__ __forceinline__ void cnot_w(float a[4], int lane) {
    cnot_p<6 - C, 6 - T>(a, lane);
}

template<int WA, int WB>
__device__ __forceinline__ void conv6(float a[4], int lane,
                                      const float2* __restrict__ cs, int base) {
    #pragma unroll
    for (int q = 0; q < 6; ++q) {
        ry_w<WA>(a, cs[base + 2 * q], lane);
        ry_w<WB>(a, cs[base + 2 * q + 1], lane);
        cnot_w<WA, WB>(a, lane);
    }
}

// ----------------------------- Kernel 1 ------------------------------
// 16 blocks x 256 threads; one warp per basis state, no per-gate barriers.
__global__ __launch_bounds__(256) void build_A_kernel(
        const float* __restrict__ QC1, const float* __restrict__ QC2,
        const float* __restrict__ QC3, const float* __restrict__ QP1,
        const float* __restrict__ QP2, const float* __restrict__ QP3,
        const float* __restrict__ QF) {
    __shared__ float2 cs[46];
    const int tid  = threadIdx.x;
    const int lane = tid & 31;
    const int basis = blockIdx.x * 8 + (tid >> 5);

    if (tid < 46) {
        float ang;
        if      (tid < 12) ang = QC1[tid];
        else if (tid < 24) ang = QC2[tid - 12];
        else if (tid < 36) ang = QC3[tid - 24];
        else if (tid == 36) ang =  QP1[0];
        else if (tid == 37) ang =  QP1[1];
        else if (tid == 38) ang = -QP1[1];
        else if (tid == 39) ang =  QP2[0];
        else if (tid == 40) ang =  QP2[1];
        else if (tid == 41) ang = -QP2[1];
        else if (tid == 42) ang =  QP3[0];
        else if (tid == 43) ang =  QP3[1];
        else if (tid == 44) ang = -QP3[1];
        else               ang = QF[0] + QF[1] + QF[2] + QF[3];  // RY angles add
        float sn, c;
        sincosf(0.5f * ang, &sn, &c);
        cs[tid] = make_float2(c, sn);
    }
    __syncthreads();   // the only barrier

    float a[4];
    #pragma unroll
    for (int r = 0; r < 4; ++r) a[r] = (lane * 4 + r == basis) ? 1.0f : 0.0f;

    // conv block 1: pairs (i, (i+1)%7)
    conv6<0,1>(a, lane, cs, 0);  conv6<1,2>(a, lane, cs, 0);
    conv6<2,3>(a, lane, cs, 0);  conv6<3,4>(a, lane, cs, 0);
    conv6<4,5>(a, lane, cs, 0);  conv6<5,6>(a, lane, cs, 0);
    conv6<6,0>(a, lane, cs, 0);
    // pool 1
    ry_w<0>(a, cs[36], lane); ry_w<3>(a, cs[37], lane);
    cnot_w<0,3>(a, lane);     ry_w<3>(a, cs[38], lane);
    ry_w<1>(a, cs[36], lane); ry_w<4>(a, cs[37], lane);
    cnot_w<1,4>(a, lane);     ry_w<4>(a, cs[38], lane);
    ry_w<2>(a, cs[36], lane); ry_w<5>(a, cs[37], lane);
    cnot_w<2,5>(a, lane);     ry_w<5>(a, cs[38], lane);
    // conv block 2
    conv6<3,4>(a, lane, cs, 12);
    conv6<4,5>(a, lane, cs, 12);
    conv6<5,6>(a, lane, cs, 12);
    #pragma unroll
    for (int q = 0; q < 6; ++q) {           // i == 6 special case
        ry_w<6>(a, cs[12 + 2 * q], lane);
        ry_w<3>(a, cs[13 + 2 * q], lane);
        cnot_w<6,0>(a, lane);
    }
    // pool 2
    ry_w<3>(a, cs[39], lane); ry_w<5>(a, cs[40], lane);
    cnot_w<3,5>(a, lane);     ry_w<5>(a, cs[41], lane);
    ry_w<4>(a, cs[39], lane); ry_w<6>(a, cs[40], lane);
    cnot_w<4,6>(a, lane);     ry_w<6>(a, cs[41], lane);
    // conv block 3 (reference bug preserved: CNOT(4,5))
    #pragma unroll
    for (int q = 0; q < 6; ++q) {
        ry_w<5>(a, cs[24 + 2 * q], lane);
        ry_w<6>(a, cs[25 + 2 * q], lane);
        cnot_w<4,5>(a, lane);
    }
    // pool 3 (reference bug preserved: CNOT(4,6))
    ry_w<5>(a, cs[42], lane); ry_w<6>(a, cs[43], lane);
    cnot_w<4,6>(a, lane);     ry_w<6>(a, cs[44], lane);
    // final: 4x RY(5) fused; CNOT(7,5)/CNOT(8,6) identity (ctrl |0>)
    ry_w<5>(a, cs[45], lane);
    cnot_w<5,6>(a, lane);
    cnot_w<6,5>(a, lane);

    reinterpret_cast<float4*>(g_AT)[basis * 32 + lane] =
        make_float4(a[0], a[1], a[2], a[3]);
}

// ----------------------------- Kernel 2 ------------------------------
// 256 blocks x 64 threads. Block = 16 batches, warp = 8 batches.
// Lane owns output rows m = 4*lane..4*lane+3 (component c == group k).
// Per iteration: 4 A-row LDS.128 (prefetched one group ahead) + 8 uniform
// X loads feed 128 FFMA -> smem wavefront pressure 24 wf / 128 FFMA.

#define APPLY_BATCH_PER_BLOCK 16
#define APPLY_THREADS 64
#define APPLY_G 8                                   // batches per warp
#define AS4_COUNT (32 * 128)                        // 64 KB
#define XS4_COUNT (APPLY_BATCH_PER_BLOCK * 32)      // 8 KB

__device__ __forceinline__ void fma4(float4& acc, float xs, const float4& a) {
    acc.x = fmaf(xs, a.x, acc.x);
    acc.y = fmaf(xs, a.y, acc.y);
    acc.z = fmaf(xs, a.z, acc.z);
    acc.w = fmaf(xs, a.w, acc.w);
}

__global__ __launch_bounds__(APPLY_THREADS) void qcnn_apply_kernel(
        const float* __restrict__ X, float* __restrict__ out) {
    extern __shared__ float sm[];
    float4* As4 = reinterpret_cast<float4*>(sm);
    float4* Xs4 = reinterpret_cast<float4*>(sm) + AS4_COUNT;

    const int tid  = threadIdx.x;
    const int warp = tid >> 5;
    const int lane = tid & 31;
    const int bbase = blockIdx.x * APPLY_BATCH_PER_BLOCK;

    // Stage A^T (64 KB) and the X tile (8 KB), coalesced float4.
    const float4* gA4 = reinterpret_cast<const float4*>(g_AT);
    #pragma unroll 8
    for (int k = 0; k < AS4_COUNT / APPLY_THREADS; ++k)
        As4[tid + k * APPLY_THREADS] = gA4[tid + k * APPLY_THREADS];
    const float4* gX4 = reinterpret_cast<const float4*>(X + (size_t)bbase * 128);
    #pragma unroll
    for (int k = 0; k < XS4_COUNT / APPLY_THREADS; ++k)
        Xs4[tid + k * APPLY_THREADS] = gX4[tid + k * APPLY_THREADS];
    __syncthreads();

    const float4* Xw   = Xs4 + warp * APPLY_G * 32;   // 8 batches per warp
    const float4* Arow = As4 + lane;                  // lane's 4 output columns

    float4 acc[APPLY_G];
    #pragma unroll
    for (int g = 0; g < APPLY_G; ++g) acc[g] = make_float4(0.f, 0.f, 0.f, 0.f);

    // Prime the A pipeline: i-group 0.
    float4 c0 = Arow[0], c1 = Arow[32], c2 = Arow[64], c3 = Arow[96];

    #pragma unroll 2
    for (int i4 = 0; i4 < 32; ++i4) {
        // Prefetch next A i-group (wraps to 0 on the last iteration).
        const int nxt = (i4 + 1) & 31;
        const float4* An = Arow + nxt * 128;
        float4 n0 = An[0], n1 = An[32], n2 = An[64], n3 = An[96];

        #pragma unroll
        for (int g = 0; g < APPLY_G; ++g) {
            const float4 xv = Xw[g * 32 + i4];   // uniform address: broadcast
            fma4(acc[g], xv.x, c0);
            fma4(acc[g], xv.y, c1);
            fma4(acc[g], xv.z, c2);
            fma4(acc[g], xv.w, c3);
        }
        c0 = n0; c1 = n1; c2 = n2; c3 = n3;
    }

    #pragma unroll
    for (int g = 0; g < APPLY_G; ++g) {
        float q0 = acc[g].x * acc[g].x;
        float q1 = acc[g].y * acc[g].y;
        float q2 = acc[g].z * acc[g].z;
        float q3 = acc[g].w * acc[g].w;
        #pragma unroll
        for (int off = 16; off; off >>= 1) {
            q0 += __shfl_xor_sync(0xffffffffu, q0, off);
            q1 += __shfl_xor_sync(0xffffffffu, q1, off);
            q2 += __shfl_xor_sync(0xffffffffu, q2, off);
            q3 += __shfl_xor_sync(0xffffffffu, q3, off);
        }
        if (lane == 0) {
            const float S = q0 + q1 + q2 + q3;   // == ||x||^2 (U orthogonal)
            const float inv_s = 1.0f / S;
            const float p0 = q0 * inv_s, p1 = q1 * inv_s;
            const float p2 = q2 * inv_s, p3 = q3 * inv_s;
            const float mx = fmaxf(fmaxf(p0, p1), fmaxf(p2, p3));
            const float e0 = expf(p0 - mx), e1 = expf(p1 - mx);
            const float e2 = expf(p2 - mx), e3 = expf(p3 - mx);
            const float inv = 1.0f / (e0 + e1 + e2 + e3);
            reinterpret_cast<float4*>(out)[bbase + warp * APPLY_G + g] =
                make_float4(e0 * inv, e1 * inv, e2 * inv, e3 * inv);
        }
    }
}

// ----------------------------- launch --------------------------------
extern "C" void kernel_launch(void* const* d_in, const int* in_sizes, int n_in,
                              void* d_out, int out_size) {
    const float* x   = (const float*)d_in[0];
    const float* QC1 = (const float*)d_in[1];
    const float* QC2 = (const float*)d_in[2];
    const float* QC3 = (const float*)d_in[3];
    const float* QP1 = (const float*)d_in[4];
    const float* QP2 = (const float*)d_in[5];
    const float* QP3 = (const float*)d_in[6];
    const float* QF  = (const float*)d_in[7];

    const int B = in_sizes[0] / 128;

    build_A_kernel<<<16, 256>>>(QC1, QC2, QC3, QP1, QP2, QP3, QF);

    const int smem_bytes = (AS4_COUNT + XS4_COUNT) * sizeof(float4);  // 72 KB
    cudaFuncSetAttribute(qcnn_apply_kernel,
                         cudaFuncAttributeMaxDynamicSharedMemorySize, smem_bytes);
    qcnn_apply_kernel<<<B / APPLY_BATCH_PER_BLOCK, APPLY_THREADS, smem_bytes>>>(
        x, (float*)d_out);
}

// round 7
// speedup vs baseline: 1.2770x; 1.0169x over previous
#include <cuda_runtime.h>
#include <cuda_bf16.h>

// =====================================================================
// ATQCNN factorization:
//   U = fixed 128x128 orthogonal circuit matrix (wires 0..6; 7,8 inert)
//   Y[b] = U x[b];  q[b,k] = sum_{m&3==k} Y[b,m]^2;  out = softmax(q/sum q)
// Kernel 1: warp-per-basis register simulation (shfl, no barriers).
// Kernel 2: 4096x128x128 fp32 GEMM w/ squared-sum + softmax epilogue.
//           R3 pipeline (g=4, A register double-buffer) + f32x2 packed
//           FMA; X pre-duplicated in smem so X reads are uniform LDS.64.
// =====================================================================

__device__ float g_AT[128 * 128];   // g_AT[i*128 + m] = <m| U |i>

// --------------------- f32x2 packed helpers ---------------------------
__device__ __forceinline__ void fma2(unsigned long long& acc,
                                     unsigned long long a,
                                     unsigned long long b) {
    asm("fma.rn.f32x2 %0, %1, %2, %0;" : "+l"(acc) : "l"(a), "l"(b));
}
__device__ __forceinline__ void unpack2(unsigned long long p, float& lo, float& hi) {
    asm("mov.b64 {%0, %1}, %2;" : "=f"(lo), "=f"(hi) : "l"(p));
}

// --------------------- gate primitives (register sim) -----------------
// Amp index m (7 bits): bits[6:2] = lane, bits[1:0] = register r.
// Bit position of wire w is P = 6 - w.

template<int P>
__device__ __forceinline__ void ry_p(float a[4], float c, float s, int lane) {
    if constexpr (P == 0) {                 // wire 6: pairs (a0,a1),(a2,a3)
        float n0 = c * a[0] - s * a[1];
        float n1 = fmaf(s, a[0], c * a[1]);
        float n2 = c * a[2] - s * a[3];
        float n3 = fmaf(s, a[2], c * a[3]);
        a[0] = n0; a[1] = n1; a[2] = n2; a[3] = n3;
    } else if constexpr (P == 1) {          // wire 5: pairs (a0,a2),(a1,a3)
        float n0 = c * a[0] - s * a[2];
        float n2 = fmaf(s, a[0], c * a[2]);
        float n1 = c * a[1] - s * a[3];
        float n3 = fmaf(s, a[1], c * a[3]);
        a[0] = n0; a[1] = n1; a[2] = n2; a[3] = n3;
    } else {                                // cross-lane wire
        constexpr int M = 1 << (P - 2);
        const float sgn = (lane & M) ? s : -s;
        #pragma unroll
        for (int r = 0; r < 4; ++r) {
            float pr = __shfl_xor_sync(0xffffffffu, a[r], M);
            a[r] = fmaf(sgn, pr, c * a[r]);
        }
    }
}

template<int W>
__device__ __forceinline__ void ry_w(float a[4], float2 cs, int lane) {
    ry_p<6 - W>(a, cs.x, cs.y, lane);
}

template<int PC, int PT>
__device__ __forceinline__ void cnot_p(float a[4], int lane) {
    if constexpr (PT >= 2) {                // target is a lane bit
        constexpr int MT = 1 << (PT - 2);
        if constexpr (PC >= 2) {            // control is a lane bit
            constexpr int MC = 1 << (PC - 2);
            const bool ctl = (lane & MC) != 0;
            #pragma unroll
            for (int r = 0; r < 4; ++r) {
                float pr = __shfl_xor_sync(0xffffffffu, a[r], MT);
                a[r] = ctl ? pr : a[r];
            }
        } else {                            // control in-register bit PC
            #pragma unroll
            for (int r = 0; r < 4; ++r) {
                if ((r >> PC) & 1) {        // compile-time constant after unroll
                    a[r] = __shfl_xor_sync(0xffffffffu, a[r], MT);
                }
            }
        }
    } else {                                // target in-register
        if constexpr (PC >= 2) {            // control is a lane bit
            constexpr int MC = 1 << (PC - 2);
            const bool ctl = (lane & MC) != 0;
            if constexpr (PT == 0) {        // swap (a0,a1) and (a2,a3)
                float t0 = a[0], t2 = a[2];
                a[0] = ctl ? a[1] : a[0];  a[1] = ctl ? t0 : a[1];
                a[2] = ctl ? a[3] : a[2];  a[3] = ctl ? t2 : a[3];
            } else {                        // PT == 1: swap (a0,a2),(a1,a3)
                float t0 = a[0], t1 = a[1];
                a[0] = ctl ? a[2] : a[0];  a[2] = ctl ? t0 : a[2];
                a[1] = ctl ? a[3] : a[1];  a[3] = ctl ? t1 : a[3];
            }
        } else {                            // both in-register
            if constexpr (PC == 1 && PT == 0) { float t = a[2]; a[2] = a[3]; a[3] = t; }
            else                              { float t = a[1]; a[1] = a[3]; a[3] = t; }
        }
    }
}

template<int C, int T>
__device__ __forceinline__ void cnot_w(float a[4], int lane) {
    cnot_p<6 - C, 6 - T>(a, lane);
}

template<int WA, int WB>
__device__ __forceinline__ void conv6(float a[4], int lane,
                                      const float2* __restrict__ cs, int base) {
    #pragma unroll
    for (int q = 0; q < 6; ++q) {
        ry_w<WA>(a, cs[base + 2 * q], lane);
        ry_w<WB>(a, cs[base + 2 * q + 1], lane);
        cnot_w<WA, WB>(a, lane);
    }
}

// ----------------------------- Kernel 1 ------------------------------
// 16 blocks x 256 threads; one warp per basis state, no per-gate barriers.
__global__ __launch_bounds__(256) void build_A_kernel(
        const float* __restrict__ QC1, const float* __restrict__ QC2,
        const float* __restrict__ QC3, const float* __restrict__ QP1,
        const float* __restrict__ QP2, const float* __restrict__ QP3,
        const float* __restrict__ QF) {
    __shared__ float2 cs[46];
    const int tid  = threadIdx.x;
    const int lane = tid & 31;
    const int basis = blockIdx.x * 8 + (tid >> 5);

    if (tid < 46) {
        float ang;
        if      (tid < 12) ang = QC1[tid];
        else if (tid < 24) ang = QC2[tid - 12];
        else if (tid < 36) ang = QC3[tid - 24];
        else if (tid == 36) ang =  QP1[0];
        else if (tid == 37) ang =  QP1[1];
        else if (tid == 38) ang = -QP1[1];
        else if (tid == 39) ang =  QP2[0];
        else if (tid == 40) ang =  QP2[1];
        else if (tid == 41) ang = -QP2[1];
        else if (tid == 42) ang =  QP3[0];
        else if (tid == 43) ang =  QP3[1];
        else if (tid == 44) ang = -QP3[1];
        else               ang = QF[0] + QF[1] + QF[2] + QF[3];  // RY angles add
        float sn, c;
        sincosf(0.5f * ang, &sn, &c);
        cs[tid] = make_float2(c, sn);
    }
    __syncthreads();   // the only barrier

    float a[4];
    #pragma unroll
    for (int r = 0; r < 4; ++r) a[r] = (lane * 4 + r == basis) ? 1.0f : 0.0f;

    // conv block 1: pairs (i, (i+1)%7)
    conv6<0,1>(a, lane, cs, 0);  conv6<1,2>(a, lane, cs, 0);
    conv6<2,3>(a, lane, cs, 0);  conv6<3,4>(a, lane, cs, 0);
    conv6<4,5>(a, lane, cs, 0);  conv6<5,6>(a, lane, cs, 0);
    conv6<6,0>(a, lane, cs, 0);
    // pool 1
    ry_w<0>(a, cs[36], lane); ry_w<3>(a, cs[37], lane);
    cnot_w<0,3>(a, lane);     ry_w<3>(a, cs[38], lane);
    ry_w<1>(a, cs[36], lane); ry_w<4>(a, cs[37], lane);
    cnot_w<1,4>(a, lane);     ry_w<4>(a, cs[38], lane);
    ry_w<2>(a, cs[36], lane); ry_w<5>(a, cs[37], lane);
    cnot_w<2,5>(a, lane);     ry_w<5>(a, cs[38], lane);
    // conv block 2
    conv6<3,4>(a, lane, cs, 12);
    conv6<4,5>(a, lane, cs, 12);
    conv6<5,6>(a, lane, cs, 12);
    #pragma unroll
    for (int q = 0; q < 6; ++q) {           // i == 6 special case
        ry_w<6>(a, cs[12 + 2 * q], lane);
        ry_w<3>(a, cs[13 + 2 * q], lane);
        cnot_w<6,0>(a, lane);
    }
    // pool 2
    ry_w<3>(a, cs[39], lane); ry_w<5>(a, cs[40], lane);
    cnot_w<3,5>(a, lane);     ry_w<5>(a, cs[41], lane);
    ry_w<4>(a, cs[39], lane); ry_w<6>(a, cs[40], lane);
    cnot_w<4,6>(a, lane);     ry_w<6>(a, cs[41], lane);
    // conv block 3 (reference bug preserved: CNOT(4,5))
    #pragma unroll
    for (int q = 0; q < 6; ++q) {
        ry_w<5>(a, cs[24 + 2 * q], lane);
        ry_w<6>(a, cs[25 + 2 * q], lane);
        cnot_w<4,5>(a, lane);
    }
    // pool 3 (reference bug preserved: CNOT(4,6))
    ry_w<5>(a, cs[42], lane); ry_w<6>(a, cs[43], lane);
    cnot_w<4,6>(a, lane);     ry_w<6>(a, cs[44], lane);
    // final: 4x RY(5) fused; CNOT(7,5)/CNOT(8,6) identity (ctrl |0>)
    ry_w<5>(a, cs[45], lane);
    cnot_w<5,6>(a, lane);
    cnot_w<6,5>(a, lane);

    reinterpret_cast<float4*>(g_AT)[basis * 32 + lane] =
        make_float4(a[0], a[1], a[2], a[3]);
}

// ----------------------------- Kernel 2 ------------------------------
// 256 blocks x 128 threads. Block = 16 batches, warp = 4 batches.
// Lane owns output rows m = 4*lane..4*lane+3 (component c == group k).
// FFMA2: A float4 viewed as 2 u64 f32x2 pairs; X pre-duplicated in smem
// ((x,x) u64 per scalar) so each X read is one uniform LDS.64.
// A register double-buffered one i-group ahead (wrap &31).

#define APPLY_BATCH_PER_BLOCK 16
#define APPLY_THREADS 128
#define APPLY_G 4
#define AS4_COUNT (32 * 128)                        // 64 KB (float4 units)
#define XD_COUNT  (APPLY_BATCH_PER_BLOCK * 128)     // 16 KB (u64 units)

__global__ __launch_bounds__(APPLY_THREADS) void qcnn_apply_kernel(
        const float* __restrict__ X, float* __restrict__ out) {
    extern __shared__ float sm[];
    float4* As4 = reinterpret_cast<float4*>(sm);                      // A tile
    unsigned long long* Xd =
        reinterpret_cast<unsigned long long*>(sm + 4 * AS4_COUNT);    // dup X

    const int tid  = threadIdx.x;
    const int warp = tid >> 5;
    const int lane = tid & 31;
    const int bbase = blockIdx.x * APPLY_BATCH_PER_BLOCK;

    // Stage A^T (64 KB), coalesced float4.
    const float4* gA4 = reinterpret_cast<const float4*>(g_AT);
    #pragma unroll 8
    for (int k = 0; k < AS4_COUNT / APPLY_THREADS; ++k)
        As4[tid + k * APPLY_THREADS] = gA4[tid + k * APPLY_THREADS];

    // Stage X duplicated: Xd[b*128 + i] = (x, x).
    const float4* gX4 = reinterpret_cast<const float4*>(X + (size_t)bbase * 128);
    float4* Xd4 = reinterpret_cast<float4*>(Xd);
    #pragma unroll
    for (int k = 0; k < (APPLY_BATCH_PER_BLOCK * 32) / APPLY_THREADS; ++k) {
        const int idx = tid + k * APPLY_THREADS;      // float4 chunk index
        const float4 v = gX4[idx];
        Xd4[2 * idx + 0] = make_float4(v.x, v.x, v.y, v.y);
        Xd4[2 * idx + 1] = make_float4(v.z, v.z, v.w, v.w);
    }
    __syncthreads();

    const unsigned long long* Xw = Xd + warp * APPLY_G * 128;  // 4 batches/warp
    const ulonglong2* Arow = reinterpret_cast<const ulonglong2*>(As4) + lane;

    // acc pairs: axy[g] = (Y[4l], Y[4l+1]), azw[g] = (Y[4l+2], Y[4l+3])
    unsigned long long axy[APPLY_G], azw[APPLY_G];
    #pragma unroll
    for (int g = 0; g < APPLY_G; ++g) { axy[g] = 0ull; azw[g] = 0ull; }

    // Prime the A pipeline: i-group 0 (rows 0..3 for this lane).
    ulonglong2 c0 = Arow[0], c1 = Arow[32], c2 = Arow[64], c3 = Arow[96];

    #pragma unroll 4
    for (int i4 = 0; i4 < 32; ++i4) {
        // Prefetch next A i-group (wraps to 0 on the last iteration).
        const int nxt = (i4 + 1) & 31;
        const ulonglong2* An = Arow + nxt * 128;
        ulonglong2 n0 = An[0], n1 = An[32], n2 = An[64], n3 = An[96];

        const int ib = i4 * 4;
        #pragma unroll
        for (int g = 0; g < APPLY_G; ++g) {
            const unsigned long long p0 = Xw[g * 128 + ib + 0];  // uniform
            const unsigned long long p1 = Xw[g * 128 + ib + 1];
            const unsigned long long p2 = Xw[g * 128 + ib + 2];
            const unsigned long long p3 = Xw[g * 128 + ib + 3];
            fma2(axy[g], p0, c0.x);  fma2(azw[g], p0, c0.y);
            fma2(axy[g], p1, c1.x);  fma2(azw[g], p1, c1.y);
            fma2(axy[g], p2, c2.x);  fma2(azw[g], p2, c2.y);
            fma2(axy[g], p3, c3.x);  fma2(azw[g], p3, c3.y);
        }
        c0 = n0; c1 = n1; c2 = n2; c3 = n3;
    }

    #pragma unroll
    for (int g = 0; g < APPLY_G; ++g) {
        float y0, y1, y2, y3;
        unpack2(axy[g], y0, y1);
        unpack2(azw[g], y2, y3);
        float q0 = y0 * y0, q1 = y1 * y1, q2 = y2 * y2, q3 = y3 * y3;
        #pragma unroll
        for (int off = 16; off; off >>= 1) {
            q0 += __shfl_xor_sync(0xffffffffu, q0, off);
            q1 += __shfl_xor_sync(0xffffffffu, q1, off);
            q2 += __shfl_xor_sync(0xffffffffu, q2, off);
            q3 += __shfl_xor_sync(0xffffffffu, q3, off);
        }
        if (lane == 0) {
            const float S = q0 + q1 + q2 + q3;   // == ||x||^2 (U orthogonal)
            const float inv_s = 1.0f / S;
            const float p0 = q0 * inv_s, p1 = q1 * inv_s;
            const float p2 = q2 * inv_s, p3 = q3 * inv_s;
            const float mx = fmaxf(fmaxf(p0, p1), fmaxf(p2, p3));
            const float e0 = expf(p0 - mx), e1 = expf(p1 - mx);
            const float e2 = expf(p2 - mx), e3 = expf(p3 - mx);
            const float inv = 1.0f / (e0 + e1 + e2 + e3);
            reinterpret_cast<float4*>(out)[bbase + warp * APPLY_G + g] =
                make_float4(e0 * inv, e1 * inv, e2 * inv, e3 * inv);
        }
    }
}

// ----------------------------- launch --------------------------------
extern "C" void kernel_launch(void* const* d_in, const int* in_sizes, int n_in,
                              void* d_out, int out_size) {
    const float* x   = (const float*)d_in[0];
    const float* QC1 = (const float*)d_in[1];
    const float* QC2 = (const float*)d_in[2];
    const float* QC3 = (const float*)d_in[3];
    const float* QP1 = (const float*)d_in[4];
    const float* QP2 = (const float*)d_in[5];
    const float* QP3 = (const float*)d_in[6];
    const float* QF  = (const float*)d_in[7];

    const int B = in_sizes[0] / 128;

    build_A_kernel<<<16, 256>>>(QC1, QC2, QC3, QP1, QP2, QP3, QF);

    const int smem_bytes = AS4_COUNT * 16 + XD_COUNT * 8;   // 64 KB + 16 KB
    cudaFuncSetAttribute(qcnn_apply_kernel,
                         cudaFuncAttributeMaxDynamicSharedMemorySize, smem_bytes);
    qcnn_apply_kernel<<<B / APPLY_BATCH_PER_BLOCK, APPLY_THREADS, smem_bytes>>>(
        x, (float*)d_out);
}